// round 7
// baseline (speedup 1.0000x reference)
#include <cuda_runtime.h>
#include <cuda_fp16.h>
#include <cstdint>

#define N_NODES 50000
#define N_EDGES 800000
#define D 128

// ---------------------------------------------------------------------------
// Device scratch
// ---------------------------------------------------------------------------
__device__ int     g_cin[N_NODES];        // deg_in  - 1 (src counts)
__device__ int     g_cnt[N_NODES];        // deg_out - 1 (dst counts)
__device__ int     g_rowptr[N_NODES + 1];
__device__ int     g_cursor[N_NODES];
__device__ int     g_col[N_EDGES];
__device__ float   g_sout[N_NODES];       // rsqrt(deg_out)
__device__ __half  g_xsh[N_NODES * D];    // fp16( x * rsqrt(deg_in) )
__device__ float   g_upd[N_NODES * D];    // aggregated update (written once)
__device__ float2  g_W2[D * (D / 2)];     // W2[k*64+j] = {W[2j][k], W[2j+1][k]}

// ---------------------------------------------------------------------------
// Packed f32x2 helpers
// ---------------------------------------------------------------------------
__device__ __forceinline__ unsigned long long pack2dup(float v) {
    unsigned long long r;
    asm("mov.b64 %0, {%1, %1};" : "=l"(r) : "f"(v));
    return r;
}
__device__ __forceinline__ void fma2(unsigned long long& d,
                                     unsigned long long a,
                                     unsigned long long b) {
    asm("fma.rn.f32x2 %0, %1, %2, %0;" : "+l"(d) : "l"(a), "l"(b));
}
__device__ __forceinline__ void unpack2(unsigned long long v, float& lo, float& hi) {
    asm("mov.b64 {%0, %1}, %2;" : "=f"(lo), "=f"(hi) : "l"(v));
}

#define ZB ((N_NODES + 255) / 256)
#define DB ((N_EDGES + 255) / 256)
#define WB ((D * (D / 2) + 255) / 256)

// ---------------------------------------------------------------------------
// Kernel 1: zero degree counters
// ---------------------------------------------------------------------------
__global__ void zero_kernel() {
    int i = blockIdx.x * blockDim.x + threadIdx.x;
    if (i < N_NODES) { g_cin[i] = 0; g_cnt[i] = 0; }
}

// ---------------------------------------------------------------------------
// Kernel 2: degree counts + W pack (disjoint block ranges)
// ---------------------------------------------------------------------------
__global__ __launch_bounds__(256) void prep2_kernel(const int2* __restrict__ edges,
                                                    const float* __restrict__ Wm) {
    int bid = blockIdx.x;
    if (bid < DB) {
        int i = bid * 256 + threadIdx.x;
        if (i < N_EDGES) {
            int2 e = edges[i];
            atomicAdd(&g_cin[e.x], 1);
            atomicAdd(&g_cnt[e.y], 1);
        }
    } else {
        int i = (bid - DB) * 256 + threadIdx.x;
        if (i < D * (D / 2)) {
            int k = i >> 6;
            int j = i & 63;
            g_W2[i] = make_float2(Wm[(2 * j) * D + k], Wm[(2 * j + 1) * D + k]);
        }
    }
}

// ---------------------------------------------------------------------------
// Kernel 3: scale.  g_xsh = fp16(x * rsqrt(deg_in));  g_sout = rsqrt(deg_out)
// ---------------------------------------------------------------------------
__global__ __launch_bounds__(256) void scale_kernel(const float* __restrict__ x) {
    int i = blockIdx.x * blockDim.x + threadIdx.x;   // float4 index
    if (i < N_NODES * (D / 4)) {
        int row = i >> 5;
        float s = rsqrtf((float)(g_cin[row] + 1));
        float4 v = reinterpret_cast<const float4*>(x)[i];
        __half2 h0 = __floats2half2_rn(v.x * s, v.y * s);
        __half2 h1 = __floats2half2_rn(v.z * s, v.w * s);
        *reinterpret_cast<__half2*>(&g_xsh[(size_t)i * 4])     = h0;
        *reinterpret_cast<__half2*>(&g_xsh[(size_t)i * 4 + 2]) = h1;
        if ((i & 31) == 0) g_sout[row] = rsqrtf((float)(g_cnt[row] + 1));
    }
}

// ---------------------------------------------------------------------------
// Kernel 4: exclusive scan of g_cnt -> rowptr, cursor. Single CTA, int4 loads.
// ---------------------------------------------------------------------------
#define SCAN_T 1024
#define SCAN_CHUNK 52     // 1024*52 = 53248 >= 50000; 52 % 4 == 0
__global__ __launch_bounds__(SCAN_T) void scan_kernel() {
    __shared__ int part[SCAN_T];
    int t = threadIdx.x;
    int base = t * SCAN_CHUNK;
    int local[SCAN_CHUNK];
    int s = 0;
#pragma unroll
    for (int i = 0; i < SCAN_CHUNK / 4; i++) {
        int idx = base + i * 4;
        int4 v = make_int4(0, 0, 0, 0);
        if (idx < N_NODES)   // N_NODES % 4 == 0, base % 4 == 0 -> full int4 valid
            v = reinterpret_cast<const int4*>(g_cnt)[idx >> 2];
        local[i * 4 + 0] = v.x; local[i * 4 + 1] = v.y;
        local[i * 4 + 2] = v.z; local[i * 4 + 3] = v.w;
        s += v.x + v.y + v.z + v.w;
    }
    part[t] = s;
    __syncthreads();
    for (int off = 1; off < SCAN_T; off <<= 1) {
        int v = (t >= off) ? part[t - off] : 0;
        __syncthreads();
        part[t] += v;
        __syncthreads();
    }
    int run = part[t] - s;   // exclusive prefix
#pragma unroll
    for (int i = 0; i < SCAN_CHUNK; i++) {
        int idx = base + i;
        if (idx < N_NODES) {
            g_rowptr[idx] = run;
            g_cursor[idx] = run;
            run += local[i];
        }
    }
    if (t == SCAN_T - 1) g_rowptr[N_NODES] = part[SCAN_T - 1];
}

// ---------------------------------------------------------------------------
// Kernel 5: fill CSR column array (order within a node arbitrary)
// ---------------------------------------------------------------------------
__global__ void fill_kernel(const int2* __restrict__ edges) {
    int i = blockIdx.x * blockDim.x + threadIdx.x;
    if (i < N_EDGES) {
        int2 e = edges[i];
        int pos = atomicAdd(&g_cursor[e.y], 1);
        g_col[pos] = e.x;
    }
}

// ---------------------------------------------------------------------------
// Kernel 6: CSR gather. 2 warps per node (half-row each); lane = __half2 pair.
//   g_upd[v] = xs[v] + sum_{(u,v)} xs[u]     (fp32 accumulate, written once)
// Edge loop unrolled 4-wide, loads batched before adds (MLP 4).
// ---------------------------------------------------------------------------
__global__ __launch_bounds__(256) void gather_kernel() {
    int gw   = (blockIdx.x * blockDim.x + threadIdx.x) >> 5;  // global warp
    int lane = threadIdx.x & 31;
    int node = gw >> 1;
    int half = gw & 1;
    if (node >= N_NODES) return;

    const __half2* xs2 = reinterpret_cast<const __half2*>(g_xsh);
    int fo = half * 32 + lane;               // half2 index within row [0,64)

    float2 acc = __half22float2(xs2[(size_t)node * 64 + fo]);   // self loop

    int s = g_rowptr[node];
    int e = g_rowptr[node + 1];
    int j = s;
    for (; j + 4 <= e; j += 4) {
        int u0 = g_col[j + 0];
        int u1 = g_col[j + 1];
        int u2 = g_col[j + 2];
        int u3 = g_col[j + 3];
        __half2 r0 = xs2[(size_t)u0 * 64 + fo];
        __half2 r1 = xs2[(size_t)u1 * 64 + fo];
        __half2 r2 = xs2[(size_t)u2 * 64 + fo];
        __half2 r3 = xs2[(size_t)u3 * 64 + fo];
        float2 f0 = __half22float2(r0);
        float2 f1 = __half22float2(r1);
        float2 f2 = __half22float2(r2);
        float2 f3 = __half22float2(r3);
        acc.x += f0.x + f1.x + f2.x + f3.x;
        acc.y += f0.y + f1.y + f2.y + f3.y;
    }
    for (; j < e; j++) {
        int u = g_col[j];
        float2 f = __half22float2(xs2[(size_t)u * 64 + fo]);
        acc.x += f.x; acc.y += f.y;
    }

    reinterpret_cast<float2*>(g_upd)[(size_t)node * 64 + fo] = acc;
}

// ---------------------------------------------------------------------------
// Kernel 7: out = relu((sout*U) @ W^T + b), packed FFMA2. (unchanged from R6)
// ---------------------------------------------------------------------------
#define GEMM_ROWS 64
__global__ __launch_bounds__(256, 3) void gemm_kernel(
    const float* __restrict__ b, float* __restrict__ out) {
    __shared__ float Us[GEMM_ROWS * D];   // 32KB

    int tid  = threadIdx.x;
    int lane = tid & 31;
    int warp = tid >> 5;
    int row0 = blockIdx.x * GEMM_ROWS;

    {
        const float4* src = reinterpret_cast<const float4*>(g_upd);
        float4* dst = reinterpret_cast<float4*>(Us);
        for (int t = tid; t < GEMM_ROWS * (D / 4); t += 256) {
            int r = t >> 5;
            int row = row0 + r;
            float4 v = make_float4(0.f, 0.f, 0.f, 0.f);
            if (row < N_NODES) {
                float s = g_sout[row];
                v = src[(size_t)row * 32 + (t & 31)];
                v.x *= s; v.y *= s; v.z *= s; v.w *= s;
            }
            dst[t] = v;
        }
    }
    __syncthreads();

    unsigned long long acc[8][2];
#pragma unroll
    for (int i = 0; i < 8; i++) { acc[i][0] = 0ull; acc[i][1] = 0ull; }

    int r0 = warp * 8;
    int j0 = lane, j1 = lane + 32;
    const float2* W2 = g_W2;

#pragma unroll
    for (int k = 0; k < D; k += 4) {
        unsigned long long wv0[4], wv1[4];
#pragma unroll
        for (int kk = 0; kk < 4; kk++) {
            float2 a = __ldg(&W2[(k + kk) * 64 + j0]);
            float2 c = __ldg(&W2[(k + kk) * 64 + j1]);
            asm("mov.b64 %0, {%1, %2};" : "=l"(wv0[kk]) : "f"(a.x), "f"(a.y));
            asm("mov.b64 %0, {%1, %2};" : "=l"(wv1[kk]) : "f"(c.x), "f"(c.y));
        }
#pragma unroll
        for (int i = 0; i < 8; i++) {
            float4 u = *reinterpret_cast<const float4*>(&Us[(r0 + i) * D + k]);
            unsigned long long u0 = pack2dup(u.x);
            unsigned long long u1 = pack2dup(u.y);
            unsigned long long u2 = pack2dup(u.z);
            unsigned long long u3 = pack2dup(u.w);
            fma2(acc[i][0], u0, wv0[0]);  fma2(acc[i][1], u0, wv1[0]);
            fma2(acc[i][0], u1, wv0[1]);  fma2(acc[i][1], u1, wv1[1]);
            fma2(acc[i][0], u2, wv0[2]);  fma2(acc[i][1], u2, wv1[2]);
            fma2(acc[i][0], u3, wv0[3]);  fma2(acc[i][1], u3, wv1[3]);
        }
    }

    float2 b0 = *reinterpret_cast<const float2*>(&b[2 * j0]);
    float2 b1 = *reinterpret_cast<const float2*>(&b[2 * j1]);
#pragma unroll
    for (int i = 0; i < 8; i++) {
        int row = row0 + r0 + i;
        if (row < N_NODES) {
            float lo, hi;
            unpack2(acc[i][0], lo, hi);
            float2 v0 = make_float2(fmaxf(lo + b0.x, 0.f), fmaxf(hi + b0.y, 0.f));
            unpack2(acc[i][1], lo, hi);
            float2 v1 = make_float2(fmaxf(lo + b1.x, 0.f), fmaxf(hi + b1.y, 0.f));
            *reinterpret_cast<float2*>(&out[(size_t)row * D + 2 * j0]) = v0;
            *reinterpret_cast<float2*>(&out[(size_t)row * D + 2 * j1]) = v1;
        }
    }
}

// ---------------------------------------------------------------------------
// Launch. Inputs: edge_list [800000,2] i32, x [50000,128] f32,
//                 W [128,128] f32, b [128] f32. Output f32 [50000,128].
// ---------------------------------------------------------------------------
extern "C" void kernel_launch(void* const* d_in, const int* in_sizes, int n_in,
                              void* d_out, int out_size) {
    const int2*  edges = (const int2*) d_in[0];
    const float* x     = (const float*)d_in[1];
    const float* Wm    = (const float*)d_in[2];
    const float* b     = (const float*)d_in[3];
    float* out = (float*)d_out;

    zero_kernel<<<ZB, 256>>>();
    prep2_kernel<<<DB + WB, 256>>>(edges, Wm);
    scale_kernel<<<(N_NODES * (D / 4) + 255) / 256, 256>>>(x);
    scan_kernel<<<1, SCAN_T>>>();
    fill_kernel<<<DB, 256>>>(edges);
    {
        int warps = N_NODES * 2;
        gather_kernel<<<(warps + 7) / 8, 256>>>();
    }
    gemm_kernel<<<(N_NODES + GEMM_ROWS - 1) / GEMM_ROWS, 256>>>(b, out);
}

// round 8
// speedup vs baseline: 1.4196x; 1.4196x over previous
#include <cuda_runtime.h>
#include <cuda_fp16.h>
#include <cstdint>

#define N_NODES 50000
#define N_EDGES 800000
#define D 128

// ---------------------------------------------------------------------------
// Device scratch
// ---------------------------------------------------------------------------
__device__ int     g_cin[N_NODES];        // deg_in  - 1 (src counts)
__device__ int     g_cnt[N_NODES];        // deg_out - 1 (dst counts)
__device__ int     g_rowptr[N_NODES + 1];
__device__ int     g_cursor[N_NODES];
__device__ int     g_col[N_EDGES];
__device__ float   g_sout[N_NODES];       // rsqrt(deg_out)
__device__ __half  g_xsh[N_NODES * D];    // fp16( x * rsqrt(deg_in) )
__device__ float   g_upd[N_NODES * D];    // aggregated update (written once)
__device__ float2  g_W2[D * (D / 2)];     // W2[k*64+j] = {W[2j][k], W[2j+1][k]}
__device__ int     g_bsum[256];           // per-block count sums (196 used)
__device__ int     g_boff[256];           // per-block exclusive offsets

// ---------------------------------------------------------------------------
// Packed f32x2 helpers
// ---------------------------------------------------------------------------
__device__ __forceinline__ unsigned long long pack2dup(float v) {
    unsigned long long r;
    asm("mov.b64 %0, {%1, %1};" : "=l"(r) : "f"(v));
    return r;
}
__device__ __forceinline__ void fma2(unsigned long long& d,
                                     unsigned long long a,
                                     unsigned long long b) {
    asm("fma.rn.f32x2 %0, %1, %2, %0;" : "+l"(d) : "l"(a), "l"(b));
}
__device__ __forceinline__ void unpack2(unsigned long long v, float& lo, float& hi) {
    asm("mov.b64 {%0, %1}, %2;" : "=f"(lo), "=f"(hi) : "l"(v));
}

#define ZB ((N_NODES + 255) / 256)        // 196
#define DB ((N_EDGES + 255) / 256)
#define WB ((D * (D / 2) + 255) / 256)

// ---------------------------------------------------------------------------
// Kernel 1: zero degree counters
// ---------------------------------------------------------------------------
__global__ void zero_kernel() {
    int i = blockIdx.x * blockDim.x + threadIdx.x;
    if (i < N_NODES) { g_cin[i] = 0; g_cnt[i] = 0; }
}

// ---------------------------------------------------------------------------
// Kernel 2: degree counts + W pack (disjoint block ranges)
// ---------------------------------------------------------------------------
__global__ __launch_bounds__(256) void prep2_kernel(const int2* __restrict__ edges,
                                                    const float* __restrict__ Wm) {
    int bid = blockIdx.x;
    if (bid < DB) {
        int i = bid * 256 + threadIdx.x;
        if (i < N_EDGES) {
            int2 e = edges[i];
            atomicAdd(&g_cin[e.x], 1);
            atomicAdd(&g_cnt[e.y], 1);
        }
    } else {
        int i = (bid - DB) * 256 + threadIdx.x;
        if (i < D * (D / 2)) {
            int k = i >> 6;
            int j = i & 63;
            g_W2[i] = make_float2(Wm[(2 * j) * D + k], Wm[(2 * j + 1) * D + k]);
        }
    }
}

// ---------------------------------------------------------------------------
// Kernel 3: scale.  g_xsh = fp16(x * rsqrt(deg_in));  g_sout = rsqrt(deg_out)
// ---------------------------------------------------------------------------
__global__ __launch_bounds__(256) void scale_kernel(const float* __restrict__ x) {
    int i = blockIdx.x * blockDim.x + threadIdx.x;   // float4 index
    if (i < N_NODES * (D / 4)) {
        int row = i >> 5;
        float s = rsqrtf((float)(g_cin[row] + 1));
        float4 v = reinterpret_cast<const float4*>(x)[i];
        __half2 h0 = __floats2half2_rn(v.x * s, v.y * s);
        __half2 h1 = __floats2half2_rn(v.z * s, v.w * s);
        *reinterpret_cast<__half2*>(&g_xsh[(size_t)i * 4])     = h0;
        *reinterpret_cast<__half2*>(&g_xsh[(size_t)i * 4 + 2]) = h1;
        if ((i & 31) == 0) g_sout[row] = rsqrtf((float)(g_cnt[row] + 1));
    }
}

// ---------------------------------------------------------------------------
// Kernels 4a/4b/4c: 3-phase multi-block exclusive scan of g_cnt.
// ---------------------------------------------------------------------------
// 4a: per-block reduction (196 blocks x 256)
__global__ __launch_bounds__(256) void scanA_kernel() {
    __shared__ int sh[8];
    int i = blockIdx.x * 256 + threadIdx.x;
    int v = (i < N_NODES) ? g_cnt[i] : 0;
    int lane = threadIdx.x & 31, warp = threadIdx.x >> 5;
#pragma unroll
    for (int o = 16; o > 0; o >>= 1) v += __shfl_down_sync(0xffffffffu, v, o);
    if (lane == 0) sh[warp] = v;
    __syncthreads();
    if (warp == 0) {
        int w = (lane < 8) ? sh[lane] : 0;
#pragma unroll
        for (int o = 4; o > 0; o >>= 1) w += __shfl_down_sync(0xffffffffu, w, o);
        if (lane == 0) g_bsum[blockIdx.x] = w;
    }
}

// 4b: scan the 196 block sums (1 block of 256)
__global__ __launch_bounds__(256) void scanB_kernel() {
    __shared__ int sh[256];
    int t = threadIdx.x;
    int v = (t < ZB) ? g_bsum[t] : 0;
    sh[t] = v;
    __syncthreads();
    for (int off = 1; off < 256; off <<= 1) {
        int a = (t >= off) ? sh[t - off] : 0;
        __syncthreads();
        sh[t] += a;
        __syncthreads();
    }
    if (t < ZB) g_boff[t] = sh[t] - v;            // exclusive
    if (t == ZB - 1) g_rowptr[N_NODES] = sh[t];   // total edge count
}

// 4c: per-block exclusive scan + global offset -> rowptr, cursor
__global__ __launch_bounds__(256) void scanC_kernel() {
    __shared__ int sh[256];
    int t = threadIdx.x;
    int i = blockIdx.x * 256 + t;
    int v = (i < N_NODES) ? g_cnt[i] : 0;
    sh[t] = v;
    __syncthreads();
    for (int off = 1; off < 256; off <<= 1) {
        int a = (t >= off) ? sh[t - off] : 0;
        __syncthreads();
        sh[t] += a;
        __syncthreads();
    }
    if (i < N_NODES) {
        int p = g_boff[blockIdx.x] + sh[t] - v;   // exclusive prefix
        g_rowptr[i] = p;
        g_cursor[i] = p;
    }
}

// ---------------------------------------------------------------------------
// Kernel 5: fill CSR column array (order within a node arbitrary)
// ---------------------------------------------------------------------------
__global__ void fill_kernel(const int2* __restrict__ edges) {
    int i = blockIdx.x * blockDim.x + threadIdx.x;
    if (i < N_EDGES) {
        int2 e = edges[i];
        int pos = atomicAdd(&g_cursor[e.y], 1);
        g_col[pos] = e.x;
    }
}

// ---------------------------------------------------------------------------
// Kernel 6: CSR gather. 2 warps per node (half-row each); lane = __half2 pair.
//   g_upd[v] = xs[v] + sum_{(u,v)} xs[u]     (fp32 accumulate, written once)
// ---------------------------------------------------------------------------
__global__ __launch_bounds__(256) void gather_kernel() {
    int gw   = (blockIdx.x * blockDim.x + threadIdx.x) >> 5;  // global warp
    int lane = threadIdx.x & 31;
    int node = gw >> 1;
    int half = gw & 1;
    if (node >= N_NODES) return;

    const __half2* xs2 = reinterpret_cast<const __half2*>(g_xsh);
    int fo = half * 32 + lane;               // half2 index within row [0,64)

    float2 acc = __half22float2(xs2[(size_t)node * 64 + fo]);   // self loop

    int s = g_rowptr[node];
    int e = g_rowptr[node + 1];
    int j = s;
    for (; j + 4 <= e; j += 4) {
        int u0 = g_col[j + 0];
        int u1 = g_col[j + 1];
        int u2 = g_col[j + 2];
        int u3 = g_col[j + 3];
        __half2 r0 = xs2[(size_t)u0 * 64 + fo];
        __half2 r1 = xs2[(size_t)u1 * 64 + fo];
        __half2 r2 = xs2[(size_t)u2 * 64 + fo];
        __half2 r3 = xs2[(size_t)u3 * 64 + fo];
        float2 f0 = __half22float2(r0);
        float2 f1 = __half22float2(r1);
        float2 f2 = __half22float2(r2);
        float2 f3 = __half22float2(r3);
        acc.x += f0.x + f1.x + f2.x + f3.x;
        acc.y += f0.y + f1.y + f2.y + f3.y;
    }
    for (; j < e; j++) {
        int u = g_col[j];
        float2 f = __half22float2(xs2[(size_t)u * 64 + fo]);
        acc.x += f.x; acc.y += f.y;
    }

    reinterpret_cast<float2*>(g_upd)[(size_t)node * 64 + fo] = acc;
}

// ---------------------------------------------------------------------------
// Kernel 7: out = relu((sout*U) @ W^T + b), packed FFMA2.
// ---------------------------------------------------------------------------
#define GEMM_ROWS 64
__global__ __launch_bounds__(256, 3) void gemm_kernel(
    const float* __restrict__ b, float* __restrict__ out) {
    __shared__ float Us[GEMM_ROWS * D];   // 32KB

    int tid  = threadIdx.x;
    int lane = tid & 31;
    int warp = tid >> 5;
    int row0 = blockIdx.x * GEMM_ROWS;

    {
        const float4* src = reinterpret_cast<const float4*>(g_upd);
        float4* dst = reinterpret_cast<float4*>(Us);
        for (int t = tid; t < GEMM_ROWS * (D / 4); t += 256) {
            int r = t >> 5;
            int row = row0 + r;
            float4 v = make_float4(0.f, 0.f, 0.f, 0.f);
            if (row < N_NODES) {
                float s = g_sout[row];
                v = src[(size_t)row * 32 + (t & 31)];
                v.x *= s; v.y *= s; v.z *= s; v.w *= s;
            }
            dst[t] = v;
        }
    }
    __syncthreads();

    unsigned long long acc[8][2];
#pragma unroll
    for (int i = 0; i < 8; i++) { acc[i][0] = 0ull; acc[i][1] = 0ull; }

    int r0 = warp * 8;
    int j0 = lane, j1 = lane + 32;
    const float2* W2 = g_W2;

#pragma unroll
    for (int k = 0; k < D; k += 4) {
        unsigned long long wv0[4], wv1[4];
#pragma unroll
        for (int kk = 0; kk < 4; kk++) {
            float2 a = __ldg(&W2[(k + kk) * 64 + j0]);
            float2 c = __ldg(&W2[(k + kk) * 64 + j1]);
            asm("mov.b64 %0, {%1, %2};" : "=l"(wv0[kk]) : "f"(a.x), "f"(a.y));
            asm("mov.b64 %0, {%1, %2};" : "=l"(wv1[kk]) : "f"(c.x), "f"(c.y));
        }
#pragma unroll
        for (int i = 0; i < 8; i++) {
            float4 u = *reinterpret_cast<const float4*>(&Us[(r0 + i) * D + k]);
            unsigned long long u0 = pack2dup(u.x);
            unsigned long long u1 = pack2dup(u.y);
            unsigned long long u2 = pack2dup(u.z);
            unsigned long long u3 = pack2dup(u.w);
            fma2(acc[i][0], u0, wv0[0]);  fma2(acc[i][1], u0, wv1[0]);
            fma2(acc[i][0], u1, wv0[1]);  fma2(acc[i][1], u1, wv1[1]);
            fma2(acc[i][0], u2, wv0[2]);  fma2(acc[i][1], u2, wv1[2]);
            fma2(acc[i][0], u3, wv0[3]);  fma2(acc[i][1], u3, wv1[3]);
        }
    }

    float2 b0 = *reinterpret_cast<const float2*>(&b[2 * j0]);
    float2 b1 = *reinterpret_cast<const float2*>(&b[2 * j1]);
#pragma unroll
    for (int i = 0; i < 8; i++) {
        int row = row0 + r0 + i;
        if (row < N_NODES) {
            float lo, hi;
            unpack2(acc[i][0], lo, hi);
            float2 v0 = make_float2(fmaxf(lo + b0.x, 0.f), fmaxf(hi + b0.y, 0.f));
            unpack2(acc[i][1], lo, hi);
            float2 v1 = make_float2(fmaxf(lo + b1.x, 0.f), fmaxf(hi + b1.y, 0.f));
            *reinterpret_cast<float2*>(&out[(size_t)row * D + 2 * j0]) = v0;
            *reinterpret_cast<float2*>(&out[(size_t)row * D + 2 * j1]) = v1;
        }
    }
}

// ---------------------------------------------------------------------------
// Launch. Inputs: edge_list [800000,2] i32, x [50000,128] f32,
//                 W [128,128] f32, b [128] f32. Output f32 [50000,128].
// ---------------------------------------------------------------------------
extern "C" void kernel_launch(void* const* d_in, const int* in_sizes, int n_in,
                              void* d_out, int out_size) {
    const int2*  edges = (const int2*) d_in[0];
    const float* x     = (const float*)d_in[1];
    const float* Wm    = (const float*)d_in[2];
    const float* b     = (const float*)d_in[3];
    float* out = (float*)d_out;

    zero_kernel<<<ZB, 256>>>();
    prep2_kernel<<<DB + WB, 256>>>(edges, Wm);
    scale_kernel<<<(N_NODES * (D / 4) + 255) / 256, 256>>>(x);
    scanA_kernel<<<ZB, 256>>>();
    scanB_kernel<<<1, 256>>>();
    scanC_kernel<<<ZB, 256>>>();
    fill_kernel<<<DB, 256>>>(edges);
    {
        int warps = N_NODES * 2;
        gather_kernel<<<(warps + 7) / 8, 256>>>();
    }
    gemm_kernel<<<(N_NODES + GEMM_ROWS - 1) / GEMM_ROWS, 256>>>(b, out);
}

// round 9
// speedup vs baseline: 1.4981x; 1.0553x over previous
#include <cuda_runtime.h>
#include <cuda_fp16.h>
#include <cstdint>

#define N_NODES 50000
#define N_EDGES 800000
#define D 128

// ---------------------------------------------------------------------------
// Device scratch
// ---------------------------------------------------------------------------
__device__ int     g_cin[N_NODES];        // deg_in  - 1 (src counts)
__device__ int     g_cnt[N_NODES];        // deg_out - 1 (dst counts)
__device__ int     g_rowptr[N_NODES + 1];
__device__ int     g_cursor[N_NODES];
__device__ int     g_col[N_EDGES];
__device__ float   g_sout[N_NODES];       // rsqrt(deg_out)
__device__ __half  g_xsh[N_NODES * D];    // fp16( x * rsqrt(deg_in) )
__device__ float2  g_W2[D * (D / 2)];     // W2[k*64+j] = {W[2j][k], W[2j+1][k]}
__device__ int     g_bsum[256];           // per-block count sums (196 used)

// ---------------------------------------------------------------------------
// Packed f32x2 helpers
// ---------------------------------------------------------------------------
__device__ __forceinline__ unsigned long long pack2dup(float v) {
    unsigned long long r;
    asm("mov.b64 %0, {%1, %1};" : "=l"(r) : "f"(v));
    return r;
}
__device__ __forceinline__ void fma2(unsigned long long& d,
                                     unsigned long long a,
                                     unsigned long long b) {
    asm("fma.rn.f32x2 %0, %1, %2, %0;" : "+l"(d) : "l"(a), "l"(b));
}
__device__ __forceinline__ void unpack2(unsigned long long v, float& lo, float& hi) {
    asm("mov.b64 {%0, %1}, %2;" : "=f"(lo), "=f"(hi) : "l"(v));
}

#define ZB ((N_NODES + 255) / 256)        // 196
#define DB ((N_EDGES + 255) / 256)        // 3125
#define WB ((D * (D / 2) + 255) / 256)    // 32
#define SB ((N_NODES * (D / 4) + 255) / 256)  // 6250 blocks for scale

// ---------------------------------------------------------------------------
// Kernel 1: zero degree counters
// ---------------------------------------------------------------------------
__global__ void zero_kernel() {
    int i = blockIdx.x * blockDim.x + threadIdx.x;
    if (i < N_NODES) { g_cin[i] = 0; g_cnt[i] = 0; }
}

// ---------------------------------------------------------------------------
// Kernel 2: degree counts + W pack (disjoint block ranges)
// ---------------------------------------------------------------------------
__global__ __launch_bounds__(256) void prep2_kernel(const int2* __restrict__ edges,
                                                    const float* __restrict__ Wm) {
    int bid = blockIdx.x;
    if (bid < DB) {
        int i = bid * 256 + threadIdx.x;
        if (i < N_EDGES) {
            int2 e = edges[i];
            atomicAdd(&g_cin[e.x], 1);
            atomicAdd(&g_cnt[e.y], 1);
        }
    } else {
        int i = (bid - DB) * 256 + threadIdx.x;
        if (i < D * (D / 2)) {
            int k = i >> 6;
            int j = i & 63;
            g_W2[i] = make_float2(Wm[(2 * j) * D + k], Wm[(2 * j + 1) * D + k]);
        }
    }
}

// ---------------------------------------------------------------------------
// Kernel 3: scale + scanA (disjoint block ranges).
//   blocks [0, SB): g_xsh = fp16(x*rsqrt(deg_in)); g_sout = rsqrt(deg_out)
//   blocks [SB, SB+ZB): per-block sums of g_cnt -> g_bsum
// ---------------------------------------------------------------------------
__global__ __launch_bounds__(256) void scale_scanA_kernel(const float* __restrict__ x) {
    int bid = blockIdx.x;
    if (bid < SB) {
        int i = bid * 256 + threadIdx.x;         // float4 index
        if (i < N_NODES * (D / 4)) {
            int row = i >> 5;
            float s = rsqrtf((float)(g_cin[row] + 1));
            float4 v = reinterpret_cast<const float4*>(x)[i];
            __half2 h0 = __floats2half2_rn(v.x * s, v.y * s);
            __half2 h1 = __floats2half2_rn(v.z * s, v.w * s);
            *reinterpret_cast<__half2*>(&g_xsh[(size_t)i * 4])     = h0;
            *reinterpret_cast<__half2*>(&g_xsh[(size_t)i * 4 + 2]) = h1;
            if ((i & 31) == 0) g_sout[row] = rsqrtf((float)(g_cnt[row] + 1));
        }
    } else {
        __shared__ int sh[8];
        int blk = bid - SB;
        int i = blk * 256 + threadIdx.x;
        int v = (i < N_NODES) ? g_cnt[i] : 0;
        int lane = threadIdx.x & 31, warp = threadIdx.x >> 5;
#pragma unroll
        for (int o = 16; o > 0; o >>= 1) v += __shfl_down_sync(0xffffffffu, v, o);
        if (lane == 0) sh[warp] = v;
        __syncthreads();
        if (warp == 0) {
            int w = (lane < 8) ? sh[lane] : 0;
#pragma unroll
            for (int o = 4; o > 0; o >>= 1) w += __shfl_down_sync(0xffffffffu, w, o);
            if (lane == 0) g_bsum[blk] = w;
        }
    }
}

// ---------------------------------------------------------------------------
// Kernel 4: fused scanB+scanC. Every block re-scans the 196 block sums in
// smem (cheap) to derive its own global offset, then does its block scan.
// ---------------------------------------------------------------------------
__global__ __launch_bounds__(256) void scanBC_kernel() {
    __shared__ int bs[256];
    __shared__ int sh[256];
    int t = threadIdx.x;

    int bv = (t < ZB) ? g_bsum[t] : 0;
    bs[t] = bv;
    __syncthreads();
    for (int off = 1; off < 256; off <<= 1) {
        int a = (t >= off) ? bs[t - off] : 0;
        __syncthreads();
        bs[t] += a;
        __syncthreads();
    }
    int boff  = (blockIdx.x > 0) ? bs[blockIdx.x - 1] : 0;  // smem broadcast
    int total = bs[ZB - 1];

    int i = blockIdx.x * 256 + t;
    int v = (i < N_NODES) ? g_cnt[i] : 0;
    sh[t] = v;
    __syncthreads();
    for (int off = 1; off < 256; off <<= 1) {
        int a = (t >= off) ? sh[t - off] : 0;
        __syncthreads();
        sh[t] += a;
        __syncthreads();
    }
    if (i < N_NODES) {
        int p = boff + sh[t] - v;     // exclusive prefix
        g_rowptr[i] = p;
        g_cursor[i] = p;
    }
    if (blockIdx.x == 0 && t == 0) g_rowptr[N_NODES] = total;
}

// ---------------------------------------------------------------------------
// Kernel 5: fill CSR column array (order within a node arbitrary)
// ---------------------------------------------------------------------------
__global__ void fill_kernel(const int2* __restrict__ edges) {
    int i = blockIdx.x * blockDim.x + threadIdx.x;
    if (i < N_EDGES) {
        int2 e = edges[i];
        int pos = atomicAdd(&g_cursor[e.y], 1);
        g_col[pos] = e.x;
    }
}

// ---------------------------------------------------------------------------
// Kernel 6: FUSED gather + GEMM.
//   Phase 1 (per warp): gather the 8 node rows this warp will compute,
//     acc = xs[v] + sum xs[u], scale by sout, store fp32 into smem U tile.
//     Lane l covers features [4l, 4l+4) (one uint2 = 2 half2 per row load).
//     Only __syncwarp needed: each warp consumes only rows it produced.
//   Phase 2: out = relu(U @ W^T + b) with packed FFMA2 (as R6-R8).
// ---------------------------------------------------------------------------
#define GEMM_ROWS 64
__global__ __launch_bounds__(256, 3) void fused_kernel(
    const float* __restrict__ b, float* __restrict__ out) {
    __shared__ float Us[GEMM_ROWS * D];   // 32KB

    int tid  = threadIdx.x;
    int lane = tid & 31;
    int warp = tid >> 5;
    int row0 = blockIdx.x * GEMM_ROWS;
    int r0   = warp * 8;

    // ---- Phase 1: gather my 8 rows ----
    {
        const __half2* xs2 = reinterpret_cast<const __half2*>(g_xsh);
        int fo = lane * 2;                     // half2 index within row [0,64)
#pragma unroll 2
        for (int i = 0; i < 8; i++) {
            int node = row0 + r0 + i;
            float2 a0 = make_float2(0.f, 0.f);
            float2 a1 = make_float2(0.f, 0.f);
            if (node < N_NODES) {
                // self loop
                uint2 raw = *reinterpret_cast<const uint2*>(&xs2[(size_t)node * 64 + fo]);
                a0 = __half22float2(*reinterpret_cast<__half2*>(&raw.x));
                a1 = __half22float2(*reinterpret_cast<__half2*>(&raw.y));
                int s = g_rowptr[node];
                int e = g_rowptr[node + 1];
                int j = s;
                for (; j + 4 <= e; j += 4) {
                    int u0 = g_col[j + 0];
                    int u1 = g_col[j + 1];
                    int u2 = g_col[j + 2];
                    int u3 = g_col[j + 3];
                    uint2 q0 = *reinterpret_cast<const uint2*>(&xs2[(size_t)u0 * 64 + fo]);
                    uint2 q1 = *reinterpret_cast<const uint2*>(&xs2[(size_t)u1 * 64 + fo]);
                    uint2 q2 = *reinterpret_cast<const uint2*>(&xs2[(size_t)u2 * 64 + fo]);
                    uint2 q3 = *reinterpret_cast<const uint2*>(&xs2[(size_t)u3 * 64 + fo]);
                    float2 f;
                    f = __half22float2(*reinterpret_cast<__half2*>(&q0.x)); a0.x += f.x; a0.y += f.y;
                    f = __half22float2(*reinterpret_cast<__half2*>(&q0.y)); a1.x += f.x; a1.y += f.y;
                    f = __half22float2(*reinterpret_cast<__half2*>(&q1.x)); a0.x += f.x; a0.y += f.y;
                    f = __half22float2(*reinterpret_cast<__half2*>(&q1.y)); a1.x += f.x; a1.y += f.y;
                    f = __half22float2(*reinterpret_cast<__half2*>(&q2.x)); a0.x += f.x; a0.y += f.y;
                    f = __half22float2(*reinterpret_cast<__half2*>(&q2.y)); a1.x += f.x; a1.y += f.y;
                    f = __half22float2(*reinterpret_cast<__half2*>(&q3.x)); a0.x += f.x; a0.y += f.y;
                    f = __half22float2(*reinterpret_cast<__half2*>(&q3.y)); a1.x += f.x; a1.y += f.y;
                }
                for (; j < e; j++) {
                    int u = g_col[j];
                    uint2 q = *reinterpret_cast<const uint2*>(&xs2[(size_t)u * 64 + fo]);
                    float2 f;
                    f = __half22float2(*reinterpret_cast<__half2*>(&q.x)); a0.x += f.x; a0.y += f.y;
                    f = __half22float2(*reinterpret_cast<__half2*>(&q.y)); a1.x += f.x; a1.y += f.y;
                }
                float so = g_sout[node];
                a0.x *= so; a0.y *= so; a1.x *= so; a1.y *= so;
            }
            *reinterpret_cast<float4*>(&Us[(r0 + i) * D + lane * 4]) =
                make_float4(a0.x, a0.y, a1.x, a1.y);
        }
    }
    __syncwarp();

    // ---- Phase 2: GEMM ----
    unsigned long long acc[8][2];
#pragma unroll
    for (int i = 0; i < 8; i++) { acc[i][0] = 0ull; acc[i][1] = 0ull; }

    int j0 = lane, j1 = lane + 32;
    const float2* W2 = g_W2;

#pragma unroll
    for (int k = 0; k < D; k += 4) {
        unsigned long long wv0[4], wv1[4];
#pragma unroll
        for (int kk = 0; kk < 4; kk++) {
            float2 a = __ldg(&W2[(k + kk) * 64 + j0]);
            float2 c = __ldg(&W2[(k + kk) * 64 + j1]);
            asm("mov.b64 %0, {%1, %2};" : "=l"(wv0[kk]) : "f"(a.x), "f"(a.y));
            asm("mov.b64 %0, {%1, %2};" : "=l"(wv1[kk]) : "f"(c.x), "f"(c.y));
        }
#pragma unroll
        for (int i = 0; i < 8; i++) {
            float4 u = *reinterpret_cast<const float4*>(&Us[(r0 + i) * D + k]);
            unsigned long long u0 = pack2dup(u.x);
            unsigned long long u1 = pack2dup(u.y);
            unsigned long long u2 = pack2dup(u.z);
            unsigned long long u3 = pack2dup(u.w);
            fma2(acc[i][0], u0, wv0[0]);  fma2(acc[i][1], u0, wv1[0]);
            fma2(acc[i][0], u1, wv0[1]);  fma2(acc[i][1], u1, wv1[1]);
            fma2(acc[i][0], u2, wv0[2]);  fma2(acc[i][1], u2, wv1[2]);
            fma2(acc[i][0], u3, wv0[3]);  fma2(acc[i][1], u3, wv1[3]);
        }
    }

    float2 b0 = *reinterpret_cast<const float2*>(&b[2 * j0]);
    float2 b1 = *reinterpret_cast<const float2*>(&b[2 * j1]);
#pragma unroll
    for (int i = 0; i < 8; i++) {
        int row = row0 + r0 + i;
        if (row < N_NODES) {
            float lo, hi;
            unpack2(acc[i][0], lo, hi);
            float2 v0 = make_float2(fmaxf(lo + b0.x, 0.f), fmaxf(hi + b0.y, 0.f));
            unpack2(acc[i][1], lo, hi);
            float2 v1 = make_float2(fmaxf(lo + b1.x, 0.f), fmaxf(hi + b1.y, 0.f));
            *reinterpret_cast<float2*>(&out[(size_t)row * D + 2 * j0]) = v0;
            *reinterpret_cast<float2*>(&out[(size_t)row * D + 2 * j1]) = v1;
        }
    }
}

// ---------------------------------------------------------------------------
// Launch. Inputs: edge_list [800000,2] i32, x [50000,128] f32,
//                 W [128,128] f32, b [128] f32. Output f32 [50000,128].
// ---------------------------------------------------------------------------
extern "C" void kernel_launch(void* const* d_in, const int* in_sizes, int n_in,
                              void* d_out, int out_size) {
    const int2*  edges = (const int2*) d_in[0];
    const float* x     = (const float*)d_in[1];
    const float* Wm    = (const float*)d_in[2];
    const float* b     = (const float*)d_in[3];
    float* out = (float*)d_out;

    zero_kernel<<<ZB, 256>>>();
    prep2_kernel<<<DB + WB, 256>>>(edges, Wm);
    scale_scanA_kernel<<<SB + ZB, 256>>>(x);
    scanBC_kernel<<<ZB, 256>>>();
    fill_kernel<<<DB, 256>>>(edges);
    fused_kernel<<<(N_NODES + GEMM_ROWS - 1) / GEMM_ROWS, 256>>>(b, out);
}